// round 6
// baseline (speedup 1.0000x reference)
#include <cuda_runtime.h>
#include <math.h>
#include <stdint.h>

// AttnPooling: B=8,N=16 -> BN=128 pairs; D=128; K=H*W=4096.
// logits l_k = q.(Wk x_k + bk) = (Wk^T q).x_k + const (const cancels in softmax)
// Pass A: masked mean -> q = Wq mean + bq -> q2 = Wk^T q / sqrt(D)
// Pass B: online softmax pooling with logits q2.x_k.
// One block per (b,n). Both passes stream the 2MB slice through a 3-stage
// cp.async.bulk ring (128 x 512B row copies per 128k-tile, mbarrier expect_tx).

#define BN 128
#define DD 128
#define KK 4096
#define TT 128
#define NTILE 32
#define NSTAGE 3
#define NTHREADS 512
#define TILE_FLOATS (DD * TT)          // 16384
#define TILE_BYTES  (TILE_FLOATS * 4)  // 65536

// smem layout (float offsets)
#define OFF_MBAR  0                     // 3 x 8B mbarriers (reserve 8 floats)
#define OFF_TILE  32                    // 128B-aligned ring
#define OFF_MASK  (OFF_TILE + NSTAGE * TILE_FLOATS)   // 49184
#define OFF_PART  (OFF_MASK + KK)                     // 53280 (16 warps x 128)
#define OFF_LOGIT (OFF_PART + 2048)
#define OFF_W     (OFF_LOGIT + 128)
#define OFF_RED   (OFF_W + 128)
#define OFF_P     (OFF_RED + 32)
#define OFF_MEAN  (OFF_P + 128)
#define OFF_Q     (OFF_MEAN + 128)
#define OFF_Q2    (OFF_Q + 128)
#define OFF_SCAL  (OFF_Q2 + 128)
#define SMEM_FLOATS (OFF_SCAL + 8)      // 56136 floats = 224544 B

__device__ __forceinline__ float warp_sum(float v) {
#pragma unroll
    for (int o = 16; o > 0; o >>= 1) v += __shfl_xor_sync(0xffffffffu, v, o);
    return v;
}
__device__ __forceinline__ float warp_max(float v) {
#pragma unroll
    for (int o = 16; o > 0; o >>= 1) v = fmaxf(v, __shfl_xor_sync(0xffffffffu, v, o));
    return v;
}
__device__ __forceinline__ uint32_t smem_u32(const void* p) {
    uint32_t a;
    asm("{ .reg .u64 t; cvta.to.shared.u64 t, %1; cvt.u32.u64 %0, t; }" : "=r"(a) : "l"(p));
    return a;
}
__device__ __forceinline__ void mbar_init(uint32_t mbar, uint32_t cnt) {
    asm volatile("mbarrier.init.shared.b64 [%0], %1;" :: "r"(mbar), "r"(cnt) : "memory");
}
__device__ __forceinline__ void mbar_wait(uint32_t mbar, uint32_t parity) {
    uint32_t done;
    asm volatile(
        "{\n\t.reg .pred p;\n\t"
        "mbarrier.try_wait.parity.acquire.cta.shared::cta.b64 p, [%1], %2;\n\t"
        "selp.b32 %0, 1, 0, p;\n\t}"
        : "=r"(done) : "r"(mbar), "r"(parity) : "memory");
    if (!done) {
        asm volatile(
            "{\n\t.reg .pred P1;\n\t"
            "W_%=:\n\t"
            "mbarrier.try_wait.parity.acquire.cta.shared::cta.b64 P1, [%0], %1, 0x989680;\n\t"
            "@P1 bra.uni D_%=;\n\t"
            "bra.uni W_%=;\n\t"
            "D_%=:\n\t}"
            :: "r"(mbar), "r"(parity) : "memory");
    }
}

// warp 0 issues one tile: expect_tx(64KB) + 128 row copies of 512B (4/lane)
__device__ __forceinline__ void issue_tile(uint32_t mbar, uint32_t dst_base,
                                           const float* __restrict__ xb,
                                           int tile_i, int lane) {
    if (lane == 0)
        asm volatile("mbarrier.arrive.expect_tx.shared.b64 _, [%0], %1;"
                     :: "r"(mbar), "r"((uint32_t)TILE_BYTES) : "memory");
    __syncwarp();
    const float* src_col = xb + (size_t)(tile_i & (NTILE - 1)) * TT;
#pragma unroll
    for (int r = 0; r < 4; r++) {
        int row = lane * 4 + r;
        uint32_t dst = dst_base + (uint32_t)row * (TT * 4);
        const float* s = src_col + (size_t)row * KK;
        asm volatile(
            "cp.async.bulk.shared::cluster.global.mbarrier::complete_tx::bytes "
            "[%0], [%1], %2, [%3];"
            :: "r"(dst), "l"(s), "r"((uint32_t)(TT * 4)), "r"(mbar) : "memory");
    }
}

__global__ void __launch_bounds__(NTHREADS, 1)
attn_pool_kernel(const float* __restrict__ x, const int* __restrict__ mask,
                 const float* __restrict__ Wq, const float* __restrict__ bq,
                 const float* __restrict__ Wk, const float* __restrict__ bk,
                 float* __restrict__ out)
{
    extern __shared__ float sm[];
    float* mask_s  = sm + OFF_MASK;
    float* part_s  = sm + OFF_PART;
    float* logit_s = sm + OFF_LOGIT;
    float* w_s     = sm + OFF_W;
    float* red_s   = sm + OFF_RED;
    float* p_s     = sm + OFF_P;
    float* mean_s  = sm + OFF_MEAN;
    float* q_s     = sm + OFF_Q;
    float* q2_s    = sm + OFF_Q2;
    float* scal    = sm + OFF_SCAL;   // [0]=count [1]=running max [2]=denom [3]=alpha

    const int tid  = threadIdx.x;
    const int lane = tid & 31;
    const int wid  = tid >> 5;
    const int bn   = blockIdx.x;
    const float NEG_INF = __int_as_float(0xff800000);

    const float* xb = x + (size_t)bn * (size_t)(DD * KK);
    const int*   mb = mask + (size_t)bn * KK;

    const uint32_t smb = smem_u32(sm);
    const uint32_t mbar0 = smb + OFF_MBAR * 4;

    // ---- init ring + prime first 3 tiles ----
    if (tid == 0) {
#pragma unroll
        for (int s = 0; s < NSTAGE; s++) mbar_init(mbar0 + s * 8, 1);
    }
    __syncthreads();
    if (wid == 0) {
#pragma unroll
        for (int s = 0; s < NSTAGE; s++)
            issue_tile(mbar0 + s * 8, smb + (OFF_TILE + s * TILE_FLOATS) * 4, xb, s, lane);
    }

    // ---- mask load + count (overlaps with fetches) ----
    float c = 0.f;
    for (int i = tid; i < KK; i += NTHREADS) {
        float v = (float)mb[i];
        mask_s[i] = v;
        c += v;
    }
    c = warp_sum(c);
    if (lane == 0) red_s[wid] = c;
    __syncthreads();
    if (wid == 0) {
        float v = (lane < 16) ? red_s[lane] : 0.f;
        v = warp_sum(v);
        if (lane == 0) scal[0] = v;
    }
    __syncthreads();

    // ---------------- Pass A: masked sums, streamed through ring ----------------
    float acc[8];
#pragma unroll
    for (int r = 0; r < 8; r++) acc[r] = 0.f;

    for (int i = 0; i < NTILE; i++) {
        const int s  = i % NSTAGE;
        const int ph = (i / NSTAGE) & 1;
        mbar_wait(mbar0 + s * 8, (uint32_t)ph);

        const float4* T4 = (const float4*)(sm + OFF_TILE + s * TILE_FLOATS);
        const float4 m4 = *(const float4*)&mask_s[i * TT + lane * 4];
#pragma unroll
        for (int r = 0; r < 8; r++) {
            const int d = wid + 16 * r;
            float4 v = T4[d * 32 + lane];
            acc[r] = fmaf(v.x, m4.x, acc[r]);
            acc[r] = fmaf(v.y, m4.y, acc[r]);
            acc[r] = fmaf(v.z, m4.z, acc[r]);
            acc[r] = fmaf(v.w, m4.w, acc[r]);
        }
        __syncthreads();   // stage s fully consumed
        if (i + NSTAGE < 2 * NTILE && wid == 0)
            issue_tile(mbar0 + s * 8, smb + (OFF_TILE + s * TILE_FLOATS) * 4,
                       xb, i + NSTAGE, lane);
    }

    // mean
    const float inv_cnt = 1.0f / scal[0];
#pragma unroll
    for (int r = 0; r < 8; r++) {
        float s = warp_sum(acc[r]);
        if (lane == 0) mean_s[wid + 16 * r] = s * inv_cnt;
    }
    __syncthreads();

    // q[d] = bq[d] + Wq[d,:].mean  (warp per row)
#pragma unroll
    for (int r = 0; r < 8; r++) {
        const int d = wid * 8 + r;
        float s = 0.f;
#pragma unroll
        for (int i = 0; i < 4; i++) {
            const int j = lane + 32 * i;
            s = fmaf(Wq[d * DD + j], mean_s[j], s);
        }
        s = warp_sum(s);
        if (lane == 0) q_s[d] = s + bq[d];
    }
    __syncthreads();

    // q2[t] = (Wk[:,t].q)/sqrt(D)
    if (tid < DD) {
        float s = 0.f;
#pragma unroll 8
        for (int j = 0; j < DD; j++)
            s = fmaf(Wk[j * DD + tid], q_s[j], s);
        q2_s[tid] = s * 0.08838834764831845f;  // 1/sqrt(128)
    }
    if (tid == 0) { scal[1] = NEG_INF; scal[3] = 0.f; }
    __syncthreads();

    // ---------------- Pass B: online-softmax pooling ----------------
    float p_dist[8];
#pragma unroll
    for (int r = 0; r < 8; r++) p_dist[r] = 0.f;
    float s_part = 0.f;

    for (int i = NTILE; i < 2 * NTILE; i++) {
        const int s  = i % NSTAGE;
        const int ph = (i / NSTAGE) & 1;
        const int t  = i - NTILE;
        mbar_wait(mbar0 + s * 8, (uint32_t)ph);

        const float4* T4 = (const float4*)(sm + OFF_TILE + s * TILE_FLOATS);

        // logit partials over this warp's 8 rows; cache tile values in regs
        float4 v4[8];
        float lx = 0.f, ly = 0.f, lz = 0.f, lw = 0.f;
#pragma unroll
        for (int r = 0; r < 8; r++) {
            const int d = wid + 16 * r;
            v4[r] = T4[d * 32 + lane];
            const float qd = q2_s[d];
            lx = fmaf(qd, v4[r].x, lx);
            ly = fmaf(qd, v4[r].y, ly);
            lz = fmaf(qd, v4[r].z, lz);
            lw = fmaf(qd, v4[r].w, lw);
        }
        *(float4*)&part_s[wid * 128 + lane * 4] = make_float4(lx, ly, lz, lw);
        __syncthreads();   // B1 — tile stage free (accum uses v4 regs)

        if (i + NSTAGE < 2 * NTILE && wid == 0)
            issue_tile(mbar0 + s * 8, smb + (OFF_TILE + s * TILE_FLOATS) * 4,
                       xb, i + NSTAGE, lane);

        // combine 16 warp-partials, mask, tile max
        float l = NEG_INF;
        if (tid < 128) {
            l = 0.f;
#pragma unroll
            for (int w = 0; w < 16; w++) l += part_s[w * 128 + tid];
            if (mask_s[t * TT + tid] == 0.f) l = NEG_INF;
            logit_s[tid] = l;
        }
        float mx = warp_max(l);
        if (tid < 128 && lane == 0) red_s[wid] = mx;
        __syncthreads();   // B2

        if (tid == 0) {
            const float tm = fmaxf(fmaxf(red_s[0], red_s[1]), fmaxf(red_s[2], red_s[3]));
            const float M  = scal[1];
            const float nM = fmaxf(M, tm);
            scal[1] = nM;
            scal[3] = (nM == NEG_INF) ? 0.f : __expf(M - nM);
        }
        __syncthreads();   // B3

        const float nM    = scal[1];
        const float alpha = scal[3];
        if (tid < 128) {
            const float w = (mask_s[t * TT + tid] != 0.f) ? __expf(logit_s[tid] - nM) : 0.f;
            w_s[tid] = w;
            s_part = fmaf(s_part, alpha, w);
        }
        __syncthreads();   // B4

        const float4 w4 = *(const float4*)&w_s[lane * 4];
#pragma unroll
        for (int r = 0; r < 8; r++) {
            float rs;
            rs = v4[r].x * w4.x;
            rs = fmaf(v4[r].y, w4.y, rs);
            rs = fmaf(v4[r].z, w4.z, rs);
            rs = fmaf(v4[r].w, w4.w, rs);
            p_dist[r] = fmaf(p_dist[r], alpha, rs);
        }
        // no trailing barrier: next tile's smem writes are ordered behind B1..B4
    }

    // ---------------- Epilogue ----------------
#pragma unroll
    for (int r = 0; r < 8; r++) {
        float rs = warp_sum(p_dist[r]);
        if (lane == 0) p_s[wid + 16 * r] = rs;
    }
    if (tid < 128) part_s[tid] = s_part;
    __syncthreads();
    if (wid == 0) {
        float v = part_s[lane] + part_s[lane + 32] + part_s[lane + 64] + part_s[lane + 96];
        v = warp_sum(v);
        if (lane == 0) scal[2] = v;
    }
    __syncthreads();
    if (tid < DD) {
        out[bn * DD + tid] = p_s[tid] / scal[2];
    }
}

extern "C" void kernel_launch(void* const* d_in, const int* in_sizes, int n_in,
                              void* d_out, int out_size) {
    const float* x    = (const float*)d_in[0];
    const int*   mask = (const int*)d_in[1];
    const float* Wq   = (const float*)d_in[2];
    const float* bq   = (const float*)d_in[3];
    const float* Wk   = (const float*)d_in[4];
    const float* bk   = (const float*)d_in[5];
    float* out = (float*)d_out;
    (void)bk; (void)in_sizes; (void)n_in; (void)out_size;  // bk cancels in softmax

    size_t smem = (size_t)SMEM_FLOATS * sizeof(float);
    cudaFuncSetAttribute(attn_pool_kernel,
                         cudaFuncAttributeMaxDynamicSharedMemorySize, (int)smem);
    attn_pool_kernel<<<BN, NTHREADS, smem>>>(x, mask, Wq, bq, Wk, bk, out);
}

// round 9
// speedup vs baseline: 2.1878x; 2.1878x over previous
#include <cuda_runtime.h>
#include <math.h>
#include <stdint.h>

// AttnPooling B=8,N=16 -> BN=128; D=128; K=4096.
// l_k = q.(Wk x_k + bk) = (Wk^T q).x_k + const (cancels in softmax).
// 4-kernel split for occupancy:
//  K1: masked partial sums over x (split-K, 4 chunks/bn)    -> g_sum, g_cnt
//  K2: mean -> q = Wq mean + bq -> q2 = Wk^T q / sqrt(D)    -> g_q2
//  K3: split-K online-softmax pooling partials              -> g_pp, g_pm, g_ps
//  K4: max-rescaled combine                                 -> out

#define BN 128
#define DD 128
#define KK 4096
#define NCH 4
#define CK  (KK / NCH)      // 1024 k per chunk
#define TT  64              // k-tile inside K3
#define NTC (CK / TT)       // 16 tiles per chunk
#define T1  256
#define T3  256

// scratch (__device__ globals: no allocation)
__device__ float g_sum[BN * NCH * DD];
__device__ float g_cnt[BN * NCH];
__device__ float g_q2[BN * DD];
__device__ float g_pp[BN * NCH * DD];
__device__ float g_pm[BN * NCH];
__device__ float g_ps[BN * NCH];

__device__ __forceinline__ float warp_sum(float v) {
#pragma unroll
    for (int o = 16; o > 0; o >>= 1) v += __shfl_xor_sync(0xffffffffu, v, o);
    return v;
}
__device__ __forceinline__ float warp_max(float v) {
#pragma unroll
    for (int o = 16; o > 0; o >>= 1) v = fmaxf(v, __shfl_xor_sync(0xffffffffu, v, o));
    return v;
}
__device__ __forceinline__ uint32_t smem_u32(const void* p) {
    uint32_t a;
    asm("{ .reg .u64 t; cvta.to.shared.u64 t, %1; cvt.u32.u64 %0, t; }" : "=r"(a) : "l"(p));
    return a;
}
__device__ __forceinline__ void cp_async16(uint32_t dst, const void* src) {
    asm volatile("cp.async.cg.shared.global [%0], [%1], 16;" :: "r"(dst), "l"(src) : "memory");
}
__device__ __forceinline__ void cp_commit() {
    asm volatile("cp.async.commit_group;" ::: "memory");
}
__device__ __forceinline__ void cp_wait0() {
    asm volatile("cp.async.wait_group 0;" ::: "memory");
}

// ---------------- K1: masked partial sums, pure streaming ----------------
__global__ void __launch_bounds__(T1, 4)
k1_masked_sum(const float* __restrict__ x, const int* __restrict__ mask)
{
    __shared__ float msk[CK];
    __shared__ float red[8];
    const int tid  = threadIdx.x;
    const int lane = tid & 31;
    const int wid  = tid >> 5;          // 8 warps
    const int c    = blockIdx.x;        // chunk
    const int bn   = blockIdx.y;

    const float* xb = x + (size_t)bn * (DD * KK) + (size_t)c * CK;
    const int*   mb = mask + (size_t)bn * KK + (size_t)c * CK;

    // mask -> smem (as float) + count
    float cnt = 0.f;
    for (int i = tid; i < CK; i += T1) {
        float v = (float)mb[i];
        msk[i] = v;
        cnt += v;
    }
    cnt = warp_sum(cnt);
    if (lane == 0) red[wid] = cnt;
    __syncthreads();
    if (tid == 0) {
        float s = 0.f;
#pragma unroll
        for (int w = 0; w < 8; w++) s += red[w];
        g_cnt[bn * NCH + c] = s;
    }

    const float4* m4 = (const float4*)msk;
    // warp wid handles rows d = wid*16 + i, i = 0..15
#pragma unroll 2
    for (int i = 0; i < 16; i++) {
        const int d = wid * 16 + i;
        const float* row = xb + (size_t)d * KK;
        float s = 0.f;
#pragma unroll
        for (int j = 0; j < 8; j++) {
            const float4 v = *(const float4*)(row + j * 128 + lane * 4);
            const float4 m = m4[j * 32 + lane];
            s = fmaf(v.x, m.x, s);
            s = fmaf(v.y, m.y, s);
            s = fmaf(v.z, m.z, s);
            s = fmaf(v.w, m.w, s);
        }
        s = warp_sum(s);
        if (lane == 0) g_sum[(bn * NCH + c) * DD + d] = s;
    }
}

// ---------------- K2: mean -> q -> q2 (tiny) ----------------
__global__ void __launch_bounds__(128)
k2_query(const float* __restrict__ Wq, const float* __restrict__ bq,
         const float* __restrict__ Wk)
{
    __shared__ float mean_s[DD];
    __shared__ float q_s[DD];
    const int tid  = threadIdx.x;
    const int lane = tid & 31;
    const int w    = tid >> 5;      // 4 warps
    const int bn   = blockIdx.x;

    float cnt = 0.f;
#pragma unroll
    for (int c = 0; c < NCH; c++) cnt += g_cnt[bn * NCH + c];
    {
        float s = 0.f;
#pragma unroll
        for (int c = 0; c < NCH; c++) s += g_sum[(bn * NCH + c) * DD + tid];
        mean_s[tid] = s / cnt;
    }
    __syncthreads();

    // q[r] = bq[r] + Wq[r,:].mean  (warp per row)
    for (int i = 0; i < 32; i++) {
        const int r = w * 32 + i;
        float s = 0.f;
#pragma unroll
        for (int b = 0; b < 4; b++) {
            const int j = lane + 32 * b;
            s = fmaf(Wq[r * DD + j], mean_s[j], s);
        }
        s = warp_sum(s);
        if (lane == 0) q_s[r] = s + bq[r];
    }
    __syncthreads();

    // q2[t] = (Wk[:,t].q)/sqrt(D)  (coalesced over t)
    float s = 0.f;
#pragma unroll 8
    for (int j = 0; j < DD; j++)
        s = fmaf(Wk[j * DD + tid], q_s[j], s);
    g_q2[bn * DD + tid] = s * 0.08838834764831845f;   // 1/sqrt(128)
}

// ---------------- K3: split-K online-softmax pooling ----------------
// smem: buf 2x(128x64) | clog 1024 | part 1024 | q2 128 | red 32  = 74368 B
#define S3_BUF   0
#define S3_CLOG  (2 * DD * TT)            // 16384
#define S3_PART  (S3_CLOG + CK)           // 17408
#define S3_Q2    (S3_PART + 1024)         // 18432
#define S3_RED   (S3_Q2 + DD)             // 18560
#define S3_FLOATS (S3_RED + 32)           // 18592

__global__ void __launch_bounds__(T3, 3)
k3_pool(const float* __restrict__ x, const int* __restrict__ mask)
{
    extern __shared__ float sm[];
    float* buf  = sm + S3_BUF;
    float* clog = sm + S3_CLOG;
    float* part = sm + S3_PART;
    float* q2s  = sm + S3_Q2;
    float* reds = sm + S3_RED;

    const int tid  = threadIdx.x;
    const int lane = tid & 31;
    const int aw   = tid >> 5;           // 8 warps
    const int c    = blockIdx.x;
    const int bn   = blockIdx.y;
    const float NEG_INF = __int_as_float(0xff800000);

    const float* xb = x + (size_t)bn * (DD * KK) + (size_t)c * CK;
    const int*   mb = mask + (size_t)bn * KK + (size_t)c * CK;
    const uint32_t bufb = smem_u32(buf);

    if (tid < DD) q2s[tid] = g_q2[bn * DD + tid];

    // per-thread mask bits for k = tid&63 across the 16 tiles
    const int kk = tid & 63;
    uint32_t mbits = 0;
#pragma unroll
    for (int t = 0; t < NTC; t++)
        mbits |= (mb[t * TT + kk] ? 1u : 0u) << t;

    // issue tile 0 into buf0: tile = 128 rows x 64 cols = 2048 float4,
    // 256 thr x 8 copies each
#pragma unroll
    for (int j = 0; j < 8; j++) {
        const int idx  = tid + T3 * j;
        const int row  = idx >> 4;
        const int col4 = idx & 15;
        cp_async16(bufb + (uint32_t)row * 256 + (uint32_t)col4 * 16,
                   xb + (size_t)row * KK + col4 * 4);
    }
    cp_commit();
    __syncthreads();          // q2s visible

    const int g  = tid >> 4;          // 16 groups
    const int k4 = tid & 15;
    float q2r[8];
#pragma unroll
    for (int j = 0; j < 8; j++) q2r[j] = q2s[g * 8 + j];

    float Mrun = NEG_INF;
    float pd[16];
#pragma unroll
    for (int i = 0; i < 16; i++) pd[i] = 0.f;

    for (int t = 0; t < NTC; t++) {
        const int cur = t & 1;
        cp_wait0();
        __syncthreads();      // S0: tile t ready, buf[cur^1] reusable

        if (t + 1 < NTC) {
            const uint32_t db = bufb + (uint32_t)(cur ^ 1) * (DD * TT * 4);
#pragma unroll
            for (int j = 0; j < 8; j++) {
                const int idx  = tid + T3 * j;
                const int row  = idx >> 4;
                const int col4 = idx & 15;
                cp_async16(db + (uint32_t)row * 256 + (uint32_t)col4 * 16,
                           xb + (size_t)row * KK + (t + 1) * TT + col4 * 4);
            }
            cp_commit();
        }

        const float* B = buf + cur * (DD * TT);
        // phase L: partial dots; group g covers rows g*8..g*8+7, cols k4*4..+3
        float ax = 0.f, ay = 0.f, az = 0.f, awf = 0.f;
#pragma unroll
        for (int j = 0; j < 8; j++) {
            const float4 v = ((const float4*)B)[(g * 8 + j) * 16 + k4];
            const float qd = q2r[j];
            ax = fmaf(qd, v.x, ax);
            ay = fmaf(qd, v.y, ay);
            az = fmaf(qd, v.z, az);
            awf = fmaf(qd, v.w, awf);
        }
        ((float4*)part)[g * 16 + k4] = make_float4(ax, ay, az, awf);
        __syncthreads();      // B1

        if (tid < TT) {
            float l = 0.f;
#pragma unroll
            for (int gg = 0; gg < 16; gg++) l += part[gg * TT + tid];
            l = ((mbits >> t) & 1u) ? l : NEG_INF;
            clog[t * TT + tid] = l;
        }
        __syncthreads();      // B2

        // per-thread running max (identical in all threads)
        const float l0 = clog[t * TT + lane];
        const float l1 = clog[t * TT + 32 + lane];
        const float tm = warp_max(fmaxf(l0, l1));
        const float nM = fmaxf(Mrun, tm);
        const float alpha = (nM == NEG_INF) ? 0.f : __expf(Mrun - nM);
        Mrun = nM;

        if (tid < TT) {
            const float lw = clog[t * TT + tid];
            part[tid] = (nM == NEG_INF) ? 0.f : __expf(lw - nM);  // w_s (part reusable)
        }
        __syncthreads();      // B3

        const float2 w2 = ((const float2*)part)[lane];
#pragma unroll
        for (int i = 0; i < 16; i++) {
            const int d = aw + 8 * i;
            const float2 v = ((const float2*)B)[d * 32 + lane];
            float rs = w2.x * v.x;
            rs = fmaf(w2.y, v.y, rs);
            pd[i] = fmaf(pd[i], alpha, rs);
        }
        // no trailing barrier: next S0 protects buffer reuse
    }

    // epilogue: pooled partial per d
#pragma unroll
    for (int i = 0; i < 16; i++) {
        const float s = warp_sum(pd[i]);
        if (lane == 0) g_pp[(bn * NCH + c) * DD + aw + 8 * i] = s;
    }
    // denominator from cached chunk logits with final max
    const float Mf = Mrun;
    float ds = 0.f;
#pragma unroll
    for (int j = 0; j < 4; j++) {
        const float l = clog[tid + T3 * j];
        ds += (Mf == NEG_INF) ? 0.f : __expf(l - Mf);
    }
    ds = warp_sum(ds);
    if (lane == 0) reds[aw] = ds;
    __syncthreads();
    if (tid == 0) {
        float s = 0.f;
#pragma unroll
        for (int w = 0; w < 8; w++) s += reds[w];
        g_ps[bn * NCH + c] = s;
        g_pm[bn * NCH + c] = Mf;
    }
}

// ---------------- K4: combine split-K softmax partials ----------------
__global__ void __launch_bounds__(128)
k4_combine(float* __restrict__ out)
{
    const int tid = threadIdx.x;
    const int bn  = blockIdx.x;
    float m[NCH];
    float M = __int_as_float(0xff800000);
#pragma unroll
    for (int c = 0; c < NCH; c++) {
        m[c] = g_pm[bn * NCH + c];
        M = fmaxf(M, m[c]);
    }
    float num = 0.f, den = 0.f;
#pragma unroll
    for (int c = 0; c < NCH; c++) {
        const float e = __expf(m[c] - M);   // exp(-inf - finite) = 0
        num = fmaf(e, g_pp[(bn * NCH + c) * DD + tid], num);
        den = fmaf(e, g_ps[bn * NCH + c], den);
    }
    out[bn * DD + tid] = num / den;
}

extern "C" void kernel_launch(void* const* d_in, const int* in_sizes, int n_in,
                              void* d_out, int out_size) {
    const float* x    = (const float*)d_in[0];
    const int*   mask = (const int*)d_in[1];
    const float* Wq   = (const float*)d_in[2];
    const float* bq   = (const float*)d_in[3];
    const float* Wk   = (const float*)d_in[4];
    const float* bk   = (const float*)d_in[5];
    float* out = (float*)d_out;
    (void)bk; (void)in_sizes; (void)n_in; (void)out_size;  // bk cancels in softmax

    size_t smem3 = (size_t)S3_FLOATS * sizeof(float);
    cudaFuncSetAttribute(k3_pool, cudaFuncAttributeMaxDynamicSharedMemorySize,
                         (int)smem3);

    dim3 gs(NCH, BN);
    k1_masked_sum<<<gs, T1>>>(x, mask);
    k2_query<<<BN, 128>>>(Wq, bq, Wk);
    k3_pool<<<gs, T3, smem3>>>(x, mask);
    k4_combine<<<BN, 128>>>(out);
}

// round 10
// speedup vs baseline: 2.4677x; 1.1280x over previous
#include <cuda_runtime.h>
#include <math.h>
#include <stdint.h>

// AttnPooling B=8,N=16 -> BN=128; D=128; K=4096.
// l_k = q.(Wk x_k + bk) = (Wk^T q).x_k + const (cancels in softmax).
// SINGLE fused kernel, 512 blocks = 128 bn-quads x 4 chunks, all resident
// (occ 4). Per block: pass A masked-sum over its 1024-k chunk -> quad atomic
// barrier -> redundant q2 compute -> pass B online-softmax pooling (3-stage
// cp.async ring, reverse tile order for L2 reuse) -> last block combines.

#define BN  128
#define DD  128
#define KK  4096
#define NCH 4
#define CK  (KK / NCH)       // 1024 k per chunk
#define TT  32               // k-tile in pass B
#define NTC (CK / TT)        // 32 tiles
#define NTH 256
#define TILE_BYTES (DD * TT * 4)   // 16384

// scratch (__device__ globals: no allocation)
__device__ float g_sum[BN * NCH * DD];
__device__ float g_cnt[BN * NCH];
__device__ float g_pp[BN * NCH * DD];
__device__ float g_pm[BN * NCH];
__device__ float g_ps[BN * NCH];
__device__ unsigned int g_sync[2 * BN];   // [0..BN) pass-A arrivals, [BN..2BN) pass-B

// smem float offsets
#define OFF_BUF  0
#define OFF_CLOG (3 * DD * TT)        // 12288 ; also pass-A mask (CK floats)
#define OFF_PART (OFF_CLOG + CK)      // 13312 ; also mean(128)+q(128)
#define OFF_Q2   (OFF_PART + 256)     // 13568
#define OFF_RED  (OFF_Q2 + DD)        // 13696
#define OFF_SCAL (OFF_RED + 32)       // 13728
#define SMF      (OFF_SCAL + 4)       // 13732 floats = 54928 B -> occ 4

__device__ __forceinline__ float warp_sum(float v) {
#pragma unroll
    for (int o = 16; o > 0; o >>= 1) v += __shfl_xor_sync(0xffffffffu, v, o);
    return v;
}
__device__ __forceinline__ float warp_max(float v) {
#pragma unroll
    for (int o = 16; o > 0; o >>= 1) v = fmaxf(v, __shfl_xor_sync(0xffffffffu, v, o));
    return v;
}
__device__ __forceinline__ uint32_t smem_u32(const void* p) {
    uint32_t a;
    asm("{ .reg .u64 t; cvta.to.shared.u64 t, %1; cvt.u32.u64 %0, t; }" : "=r"(a) : "l"(p));
    return a;
}
__device__ __forceinline__ void cp_async16(uint32_t dst, const void* src) {
    asm volatile("cp.async.cg.shared.global [%0], [%1], 16;" :: "r"(dst), "l"(src) : "memory");
}
__device__ __forceinline__ void cp_commit() {
    asm volatile("cp.async.commit_group;" ::: "memory");
}
__device__ __forceinline__ void cp_wait0() {
    asm volatile("cp.async.wait_group 0;" ::: "memory");
}
__device__ __forceinline__ void cp_wait1() {
    asm volatile("cp.async.wait_group 1;" ::: "memory");
}

// one tile = 128 rows x 32 floats = 1024 float4; 256 thr x 4 copies
__device__ __forceinline__ void issue_tile(uint32_t base, const float* __restrict__ xb,
                                           int rt, int tid) {
#pragma unroll
    for (int j = 0; j < 4; j++) {
        const int idx = tid + NTH * j;
        const int row = idx >> 3;
        const int c4  = idx & 7;
        cp_async16(base + (uint32_t)row * (TT * 4) + (uint32_t)c4 * 16,
                   xb + (size_t)row * KK + rt * TT + c4 * 4);
    }
}

__global__ void __launch_bounds__(NTH, 4)
fused_attn_pool(const float* __restrict__ x, const int* __restrict__ mask,
                const float* __restrict__ Wq, const float* __restrict__ bq,
                const float* __restrict__ Wk, float* __restrict__ out)
{
    extern __shared__ float sm[];
    float* buf  = sm + OFF_BUF;
    float* clog = sm + OFF_CLOG;      // pass A: mask; pass B: chunk logits
    float* part = sm + OFF_PART;      // pass L partials; also mean(0..127)+q(128..255)
    float* q2s  = sm + OFF_Q2;
    float* reds = sm + OFF_RED;
    float* scal = sm + OFF_SCAL;

    const int tid  = threadIdx.x;
    const int lane = tid & 31;
    const int aw   = tid >> 5;        // 8 warps
    const int bn   = blockIdx.x >> 2;
    const int c    = blockIdx.x & 3;
    const float NEG_INF = __int_as_float(0xff800000);

    const float* xb = x + (size_t)bn * (DD * KK) + (size_t)c * CK;
    const int*   mb = mask + (size_t)bn * KK + (size_t)c * CK;
    const uint32_t bufb = smem_u32(buf);

    // ================= pass A: mask + masked partial sums =================
    float* msk = clog;                // CK floats
    float cnt = 0.f;
    for (int i = tid; i < CK; i += NTH) {
        const float v = (float)mb[i];
        msk[i] = v;
        cnt += v;
    }
    cnt = warp_sum(cnt);
    if (lane == 0) reds[aw] = cnt;
    __syncthreads();
    if (tid == 0) {
        float s = 0.f;
#pragma unroll
        for (int w = 0; w < 8; w++) s += reds[w];
        g_cnt[bn * NCH + c] = s;
    }

    const float4* m4 = (const float4*)msk;
#pragma unroll 2
    for (int i = 0; i < 16; i++) {
        const int d = aw * 16 + i;
        const float* row = xb + (size_t)d * KK;
        float s = 0.f;
#pragma unroll
        for (int j = 0; j < 8; j++) {
            const float4 v = *(const float4*)(row + j * 128 + lane * 4);
            const float4 m = m4[j * 32 + lane];
            s = fmaf(v.x, m.x, s);
            s = fmaf(v.y, m.y, s);
            s = fmaf(v.z, m.z, s);
            s = fmaf(v.w, m.w, s);
        }
        s = warp_sum(s);
        if (lane == 0) g_sum[(bn * NCH + c) * DD + d] = s;
    }
    __syncthreads();   // all g_sum/g_cnt stores issued

    // prefetch first two pass-B tiles (reverse order) — overlaps quad sync
    issue_tile(bufb,              xb, NTC - 1, tid); cp_commit();
    issue_tile(bufb + TILE_BYTES, xb, NTC - 2, tid); cp_commit();

    // ============== quad barrier (4 chunk-blocks of this bn) ==============
    if (tid == 0) {
        __threadfence();
        atomicAdd(&g_sync[bn], 1u);
        while (((volatile unsigned int*)g_sync)[bn] < (unsigned)NCH) __nanosleep(64);
        __threadfence();
    }
    __syncthreads();

    // ============== redundant q2 compute (per block) ==============
    float* mean_s = part;            // [0..127]
    float* q_s    = part + 128;      // [128..255]
    if (tid < DD) {
        float cs = 0.f, ss = 0.f;
#pragma unroll
        for (int c2 = 0; c2 < NCH; c2++) {
            cs += g_cnt[bn * NCH + c2];
            ss += g_sum[(bn * NCH + c2) * DD + tid];
        }
        mean_s[tid] = ss / cs;
    }
    __syncthreads();
#pragma unroll 2
    for (int ii = 0; ii < 16; ii++) {
        const int r = aw * 16 + ii;
        float s = 0.f;
#pragma unroll
        for (int b = 0; b < 4; b++) {
            const int j = lane + 32 * b;
            s = fmaf(Wq[r * DD + j], mean_s[j], s);
        }
        s = warp_sum(s);
        if (lane == 0) q_s[r] = s + bq[r];
    }
    __syncthreads();
    if (tid < DD) {
        float s = 0.f;
#pragma unroll 8
        for (int j = 0; j < DD; j++)
            s = fmaf(Wk[j * DD + tid], q_s[j], s);
        q2s[tid] = s * 0.08838834764831845f;   // 1/sqrt(128)
    }
    // mask bits for warp 0 (k = tid, bit t = tile t) — read before clog reuse
    uint32_t mbits = 0;
    if (tid < TT) {
#pragma unroll
        for (int t = 0; t < NTC; t++)
            mbits |= (msk[t * TT + tid] != 0.f ? 1u : 0u) << t;
    }
    __syncthreads();   // q2s visible; mean/q dead

    // ================= pass B: online softmax, reverse tiles =================
    float Mrun = NEG_INF;
    float pd[16];
#pragma unroll
    for (int i = 0; i < 16; i++) pd[i] = 0.f;

    for (int i = 0; i < NTC; i++) {
        const int rt = NTC - 1 - i;        // actual tile (reverse for L2 reuse)
        const int st = i % 3;
        if (i == NTC - 1) cp_wait0(); else cp_wait1();
        __syncthreads();   // S0: tile i ready; stage (i%3) from i-3 fully consumed

        if (i + 2 < NTC) {
            issue_tile(bufb + (uint32_t)((i + 2) % 3) * TILE_BYTES,
                       xb, NTC - 1 - (i + 2), tid);
            cp_commit();
        }

        const float* B = buf + st * (DD * TT);
        // phase L: warp aw covers d = aw*16..+15, k = lane
        {
            float acc = 0.f;
#pragma unroll
            for (int j = 0; j < 16; j++) {
                const int d = aw * 16 + j;
                acc = fmaf(q2s[d], B[d * TT + lane], acc);
            }
            part[aw * TT + lane] = acc;
        }
        __syncthreads();   // B1

        if (tid < TT) {
            float l = 0.f;
#pragma unroll
            for (int g = 0; g < 8; g++) l += part[g * TT + tid];
            l = ((mbits >> rt) & 1u) ? l : NEG_INF;
            clog[rt * TT + tid] = l;
        }
        __syncthreads();   // B2

        // every warp redundantly: tile max, alpha, weights (no extra barrier)
        const float lr = clog[rt * TT + lane];
        const float tm = warp_max(lr);
        const float nM = fmaxf(Mrun, tm);
        const float alpha = (nM == NEG_INF) ? 0.f : __expf(Mrun - nM);
        const float w     = (nM == NEG_INF) ? 0.f : __expf(lr - nM);
        Mrun = nM;

#pragma unroll
        for (int ii = 0; ii < 16; ii++) {
            const int d = aw * 16 + ii;
            pd[ii] = fmaf(pd[ii], alpha, w * B[d * TT + lane]);
        }
        // next iteration's S0 protects stage reuse
    }

    // ================= epilogue: partials + last-block combine =================
#pragma unroll
    for (int ii = 0; ii < 16; ii++) {
        const float s = warp_sum(pd[ii]);
        if (lane == 0) g_pp[(bn * NCH + c) * DD + aw * 16 + ii] = s;
    }
    const float Mf = Mrun;
    float ds = 0.f;
#pragma unroll
    for (int j = 0; j < 4; j++) {
        const float l = clog[tid + NTH * j];
        ds += (Mf == NEG_INF) ? 0.f : __expf(l - Mf);
    }
    ds = warp_sum(ds);
    if (lane == 0) reds[aw] = ds;
    __syncthreads();
    if (tid == 0) {
        float s = 0.f;
#pragma unroll
        for (int w = 0; w < 8; w++) s += reds[w];
        g_ps[bn * NCH + c] = s;
        g_pm[bn * NCH + c] = Mf;
        __threadfence();
        const unsigned old = atomicAdd(&g_sync[BN + bn], 1u);
        ((unsigned*)scal)[0] = old;
    }
    __syncthreads();

    if (((const unsigned*)scal)[0] == (unsigned)(NCH - 1)) {
        __threadfence();   // acquire: partials from sibling blocks
        if (tid < DD) {
            float pm[NCH];
            float M = NEG_INF;
#pragma unroll
            for (int c2 = 0; c2 < NCH; c2++) {
                pm[c2] = g_pm[bn * NCH + c2];
                M = fmaxf(M, pm[c2]);
            }
            float num = 0.f, den = 0.f;
#pragma unroll
            for (int c2 = 0; c2 < NCH; c2++) {
                const float e = __expf(pm[c2] - M);   // exp(-inf - finite) = 0
                num = fmaf(e, g_pp[(bn * NCH + c2) * DD + tid], num);
                den = fmaf(e, g_ps[bn * NCH + c2], den);
            }
            out[bn * DD + tid] = num / den;
        }
    }
}

extern "C" void kernel_launch(void* const* d_in, const int* in_sizes, int n_in,
                              void* d_out, int out_size) {
    const float* x    = (const float*)d_in[0];
    const int*   mask = (const int*)d_in[1];
    const float* Wq   = (const float*)d_in[2];
    const float* bq   = (const float*)d_in[3];
    const float* Wk   = (const float*)d_in[4];
    const float* bk   = (const float*)d_in[5];
    float* out = (float*)d_out;
    (void)bk; (void)in_sizes; (void)n_in; (void)out_size;  // bk cancels in softmax

    void* sp = nullptr;
    cudaGetSymbolAddress(&sp, g_sync);
    cudaMemsetAsync(sp, 0, 2 * BN * sizeof(unsigned int));

    const size_t smem = (size_t)SMF * sizeof(float);
    cudaFuncSetAttribute(fused_attn_pool,
                         cudaFuncAttributeMaxDynamicSharedMemorySize, (int)smem);
    fused_attn_pool<<<BN * NCH, NTH, smem>>>(x, mask, Wq, bq, Wk, out);
}